// round 17
// baseline (speedup 1.0000x reference)
#include <cuda_runtime.h>
#include <math.h>

#define H    256
#define H2   512
#define SEQ  256
#define NL   4
#define VOC  50257
#define TPB  512
#define NWARP 16
#define CHB  8                           // chain blocks (one 8-CTA cluster)

#define GEMV_GRID 148
#define GEMV_TOTW (GEMV_GRID * NWARP)    // 2368
#define GEMV_ITERS 3                     // 3*2368*8 = 56832 >= VOC

// ---------------- scratch (device globals; no allocation allowed) ----------
__device__ __align__(16) float  g_attn_logits[SEQ];
__device__ __align__(16) float  g_xbuf[2][H];
__device__ __align__(16) float2 g_red[GEMV_GRID];

// ---------------- PDL / cluster helpers -------------------------------------
__device__ __forceinline__ void pdl_wait() {
    asm volatile("griddepcontrol.wait;" ::: "memory");
}
__device__ __forceinline__ void pdl_trigger() {
    asm volatile("griddepcontrol.launch_dependents;" ::: "memory");
}
__device__ __forceinline__ void cl_arrive() {
    asm volatile("barrier.cluster.arrive.aligned;" ::: "memory");
}
__device__ __forceinline__ void cl_wait() {
    asm volatile("barrier.cluster.wait.aligned;" ::: "memory");
}

// ---------------- math helpers ----------------------------------------------
__device__ __forceinline__ float dot4f(float4 a, float4 b) {
    return fmaf(a.x, b.x, fmaf(a.y, b.y, fmaf(a.z, b.z, a.w * b.w)));
}
// packed 4-row warp reduce: lanes 0-7 hold full sum of d0, 8-15 d1, 16-23 d2,
// 24-31 d3.
__device__ __forceinline__ float red4(float d0, float d1, float d2, float d3, int lane) {
    bool h16 = (lane & 16) != 0, h8 = (lane & 8) != 0;
    float k0 = (h16 ? d2 : d0) + __shfl_xor_sync(0xffffffffu, h16 ? d0 : d2, 16);
    float k1 = (h16 ? d3 : d1) + __shfl_xor_sync(0xffffffffu, h16 ? d1 : d3, 16);
    float v  = (h8 ? k1 : k0) + __shfl_xor_sync(0xffffffffu, h8 ? k0 : k1, 8);
    v += __shfl_xor_sync(0xffffffffu, v, 4);
    v += __shfl_xor_sync(0xffffffffu, v, 2);
    v += __shfl_xor_sync(0xffffffffu, v, 1);
    return v;
}
// packed 8-row warp reduce: every lane ends with full sum of row (lane>>2);
// owner = (lane&3)==0.
__device__ __forceinline__ float red8(const float* d, int lane) {
    bool h16 = (lane & 16) != 0, h8 = (lane & 8) != 0, h4b = (lane & 4) != 0;
    float k0 = (h16 ? d[4] : d[0]) + __shfl_xor_sync(0xffffffffu, h16 ? d[0] : d[4], 16);
    float k1 = (h16 ? d[5] : d[1]) + __shfl_xor_sync(0xffffffffu, h16 ? d[1] : d[5], 16);
    float k2 = (h16 ? d[6] : d[2]) + __shfl_xor_sync(0xffffffffu, h16 ? d[2] : d[6], 16);
    float k3 = (h16 ? d[7] : d[3]) + __shfl_xor_sync(0xffffffffu, h16 ? d[3] : d[7], 16);
    float m0 = (h8 ? k2 : k0) + __shfl_xor_sync(0xffffffffu, h8 ? k0 : k2, 8);
    float m1 = (h8 ? k3 : k1) + __shfl_xor_sync(0xffffffffu, h8 ? k1 : k3, 8);
    float v  = (h4b ? m1 : m0) + __shfl_xor_sync(0xffffffffu, h4b ? m0 : m1, 4);
    v += __shfl_xor_sync(0xffffffffu, v, 2);
    v += __shfl_xor_sync(0xffffffffu, v, 1);
    return v;
}

// ===== K1: full serial chain in ONE 8-CTA cluster kernel (grid 8 x 512) =====
__global__ void __launch_bounds__(TPB, 1) __cluster_dims__(CHB, 1, 1)
k_chain(const int* __restrict__ token,
        const float* __restrict__ hidden,
        const float* __restrict__ enc,
        const float* __restrict__ emb,
        const float* __restrict__ attn_w,
        const float* __restrict__ attn_b,
        const float* __restrict__ comb_w,
        const float* __restrict__ comb_b,
        const float* __restrict__ gru_wih,
        const float* __restrict__ gru_whh,
        const float* __restrict__ gru_bih,
        const float* __restrict__ gru_bhh,
        float* __restrict__ out)
{
    const int tid = threadIdx.x, bid = blockIdx.x;
    const int wid = tid >> 5, lane = tid & 31;
    __shared__ __align__(16) float s_in[H2];
    __shared__ __align__(16) float s_x[H];
    __shared__ __align__(16) float s_aw[SEQ];
    __shared__ __align__(16) float s_part[NWARP][H];
    __shared__ float s_red[NWARP];
    __shared__ float s_bc[2];

    const int j0 = (bid * NWARP + wid) * 2;   // this warp's 2 rows
    const int j1 = j0 + 1;

    // ================= Phase L: attention logits (2 rows/warp) ==============
    {
        const int tok = token[0];
        const float* erow = emb + (size_t)tok * H;
        s_in[tid] = (tid < H) ? __ldg(erow + tid) : __ldg(hidden + tid - H);
        __syncthreads();
        const float4* in4 = (const float4*)s_in;
        float4 xv[4];
        #pragma unroll
        for (int t = 0; t < 4; t++) xv[t] = in4[lane + 32 * t];
        const float4* w0 = (const float4*)(attn_w + (size_t)j0 * H2);
        const float4* w1 = (const float4*)(attn_w + (size_t)j1 * H2);
        float d0 = 0.f, d1 = 0.f;
        #pragma unroll
        for (int t = 0; t < 4; t++) {
            d0 += dot4f(__ldg(w0 + lane + 32 * t), xv[t]);
            d1 += dot4f(__ldg(w1 + lane + 32 * t), xv[t]);
        }
        float v = red4(d0, d1, 0.f, 0.f, lane);
        if (lane == 0) __stcg(&g_attn_logits[j0], v + __ldg(attn_b + j0));
        if (lane == 8) __stcg(&g_attn_logits[j1], v + __ldg(attn_b + j1));
    }
    __threadfence();
    cl_arrive();

    // ---- window: gh(layer 0) for rows j0,j1 + comb weights (x-independent) -
    float p_ghr0, p_ghz0, p_ghn0, p_ghr1, p_ghz1, p_ghn1;
    float4 CA[8];
    {
        const float4* h4 = (const float4*)hidden;   // hidden[0]
        float4 ha = __ldg(h4 + lane), hb = __ldg(h4 + lane + 32);
        const float* whh = gru_whh;
        const float4* vr0 = (const float4*)(whh + (size_t)j0 * H);
        const float4* vz0 = (const float4*)(whh + (size_t)(H + j0) * H);
        const float4* vn0 = (const float4*)(whh + (size_t)(2 * H + j0) * H);
        const float4* vr1 = (const float4*)(whh + (size_t)j1 * H);
        const float4* vz1 = (const float4*)(whh + (size_t)(H + j1) * H);
        const float4* vn1 = (const float4*)(whh + (size_t)(2 * H + j1) * H);
        float hr0 = dot4f(__ldg(vr0 + lane), ha) + dot4f(__ldg(vr0 + lane + 32), hb);
        float hz0 = dot4f(__ldg(vz0 + lane), ha) + dot4f(__ldg(vz0 + lane + 32), hb);
        float hn0 = dot4f(__ldg(vn0 + lane), ha) + dot4f(__ldg(vn0 + lane + 32), hb);
        float hr1 = dot4f(__ldg(vr1 + lane), ha) + dot4f(__ldg(vr1 + lane + 32), hb);
        float hz1 = dot4f(__ldg(vz1 + lane), ha) + dot4f(__ldg(vz1 + lane + 32), hb);
        float hn1 = dot4f(__ldg(vn1 + lane), ha) + dot4f(__ldg(vn1 + lane + 32), hb);
        float v1 = red4(hr0, hz0, hn0, 0.f, lane);
        float v2 = red4(hr1, hz1, hn1, 0.f, lane);
        p_ghr0 = __shfl_sync(0xffffffffu, v1, 0)  + __ldg(gru_bhh + 0 * H + j0);
        p_ghz0 = __shfl_sync(0xffffffffu, v1, 8)  + __ldg(gru_bhh + 1 * H + j0);
        p_ghn0 = __shfl_sync(0xffffffffu, v1, 16) + __ldg(gru_bhh + 2 * H + j0);
        p_ghr1 = __shfl_sync(0xffffffffu, v2, 0)  + __ldg(gru_bhh + 0 * H + j1);
        p_ghz1 = __shfl_sync(0xffffffffu, v2, 8)  + __ldg(gru_bhh + 1 * H + j1);
        p_ghn1 = __shfl_sync(0xffffffffu, v2, 16) + __ldg(gru_bhh + 2 * H + j1);
        const float4* c0 = (const float4*)(comb_w + (size_t)j0 * H2);
        const float4* c1 = (const float4*)(comb_w + (size_t)j1 * H2);
        #pragma unroll
        for (int t = 0; t < 4; t++) {
            CA[t]     = __ldg(c0 + lane + 32 * t);
            CA[4 + t] = __ldg(c1 + lane + 32 * t);
        }
    }
    cl_wait();   // logits visible cluster-wide

    // ================= Phase S: softmax (redundant per block) ===============
    {
        float v = (tid < SEQ) ? __ldcg(&g_attn_logits[tid]) : -1e30f;
        float wm = v;
        #pragma unroll
        for (int o = 16; o; o >>= 1) wm = fmaxf(wm, __shfl_xor_sync(0xffffffffu, wm, o));
        if (lane == 0) s_red[wid] = wm;
        __syncthreads();
        if (tid == 0) {
            float m = s_red[0];
            #pragma unroll
            for (int w = 1; w < NWARP; w++) m = fmaxf(m, s_red[w]);
            s_bc[0] = m;
        }
        __syncthreads();
        float ex = (tid < SEQ) ? expf(v - s_bc[0]) : 0.f;
        float ws = ex;
        #pragma unroll
        for (int o = 16; o; o >>= 1) ws += __shfl_xor_sync(0xffffffffu, ws, o);
        if (lane == 0) s_red[wid] = ws;
        __syncthreads();
        if (tid == 0) {
            float s = 0.f;
            #pragma unroll
            for (int w = 0; w < NWARP; w++) s += s_red[w];
            s_bc[1] = s;
        }
        __syncthreads();
        float aw = ex / s_bc[1];
        if (tid < SEQ) s_aw[tid] = aw;
        __syncthreads();
    }

    // ============ Phase A: attn_applied (redundant per block) ===============
    {
        float acc[8];
        #pragma unroll
        for (int c8 = 0; c8 < 8; c8++) acc[c8] = 0.f;
        int i0 = wid * 16;
        #pragma unroll 4
        for (int ii = 0; ii < 16; ii++) {
            float a = s_aw[i0 + ii];
            const float* er = enc + (size_t)(i0 + ii) * H;
            #pragma unroll
            for (int c8 = 0; c8 < 8; c8++)
                acc[c8] = fmaf(a, __ldg(er + c8 * 32 + lane), acc[c8]);
        }
        #pragma unroll
        for (int c8 = 0; c8 < 8; c8++) s_part[wid][c8 * 32 + lane] = acc[c8];
    }
    __syncthreads();
    if (tid < H) {
        float ap = 0.f;
        #pragma unroll
        for (int w = 0; w < NWARP; w++) ap += s_part[w][tid];
        s_in[H + tid] = ap;     // emb half of s_in still intact
    }
    __syncthreads();

    // ================= Phase C: comb (2 rows/warp) ==========================
    {
        const float4* in4 = (const float4*)s_in;
        float4 xv[4];
        #pragma unroll
        for (int t = 0; t < 4; t++) xv[t] = in4[lane + 32 * t];
        float d0 = 0.f, d1 = 0.f;
        #pragma unroll
        for (int t = 0; t < 4; t++) {
            d0 += dot4f(CA[t], xv[t]);
            d1 += dot4f(CA[4 + t], xv[t]);
        }
        float v = red4(d0, d1, 0.f, 0.f, lane);
        if (lane == 0) __stcg(&g_xbuf[0][j0], fmaxf(v + __ldg(comb_b + j0), 0.f));
        if (lane == 8) __stcg(&g_xbuf[0][j1], fmaxf(v + __ldg(comb_b + j1), 0.f));
    }
    __threadfence();
    cl_arrive();

    // ---- window: layer-0 wih weights + epilogue scalars --------------------
    float4 W[12];
    float p_br0, p_bz0, p_bn0, p_br1, p_bz1, p_bn1, p_h0, p_h1;
    {
        const float* wih = gru_wih;
        const float4* r0 = (const float4*)(wih + (size_t)j0 * H);
        const float4* z0 = (const float4*)(wih + (size_t)(H + j0) * H);
        const float4* n0 = (const float4*)(wih + (size_t)(2 * H + j0) * H);
        const float4* r1 = (const float4*)(wih + (size_t)j1 * H);
        const float4* z1 = (const float4*)(wih + (size_t)(H + j1) * H);
        const float4* n1 = (const float4*)(wih + (size_t)(2 * H + j1) * H);
        W[0] = __ldg(r0 + lane); W[1] = __ldg(r0 + lane + 32);
        W[2] = __ldg(z0 + lane); W[3] = __ldg(z0 + lane + 32);
        W[4] = __ldg(n0 + lane); W[5] = __ldg(n0 + lane + 32);
        W[6] = __ldg(r1 + lane); W[7] = __ldg(r1 + lane + 32);
        W[8] = __ldg(z1 + lane); W[9] = __ldg(z1 + lane + 32);
        W[10] = __ldg(n1 + lane); W[11] = __ldg(n1 + lane + 32);
        p_br0 = __ldg(gru_bih + 0 * H + j0);
        p_bz0 = __ldg(gru_bih + 1 * H + j0);
        p_bn0 = __ldg(gru_bih + 2 * H + j0);
        p_br1 = __ldg(gru_bih + 0 * H + j1);
        p_bz1 = __ldg(gru_bih + 1 * H + j1);
        p_bn1 = __ldg(gru_bih + 2 * H + j1);
        p_h0 = __ldg(hidden + j0);
        p_h1 = __ldg(hidden + j1);
    }
    cl_wait();   // x0 visible cluster-wide

    // ================= GRU layers (2 rows/warp, pipelined) ==================
    #pragma unroll 1
    for (int l = 0; l < NL; l++) {
        if (tid < H) s_x[tid] = __ldcg(&g_xbuf[l & 1][tid]);
        __syncthreads();
        const float4* x4 = (const float4*)s_x;
        float4 xa = x4[lane], xb = x4[lane + 32];
        float dr0 = dot4f(W[0], xa) + dot4f(W[1], xb);
        float dz0 = dot4f(W[2], xa) + dot4f(W[3], xb);
        float dn0 = dot4f(W[4], xa) + dot4f(W[5], xb);
        float dr1 = dot4f(W[6], xa) + dot4f(W[7], xb);
        float dz1 = dot4f(W[8], xa) + dot4f(W[9], xb);
        float dn1 = dot4f(W[10], xa) + dot4f(W[11], xb);
        float v1 = red4(dr0, dz0, dn0, 0.f, lane);
        float v2 = red4(dr1, dz1, dn1, 0.f, lane);
        float rs0 = __shfl_sync(0xffffffffu, v1, 0);
        float zs0 = __shfl_sync(0xffffffffu, v1, 8);
        float ns0 = __shfl_sync(0xffffffffu, v1, 16);
        float rs1 = __shfl_sync(0xffffffffu, v2, 0);
        float zs1 = __shfl_sync(0xffffffffu, v2, 8);
        float ns1 = __shfl_sync(0xffffffffu, v2, 16);
        if (lane == 0) {
            float r0 = 1.f / (1.f + expf(-((rs0 + p_br0) + p_ghr0)));
            float z0 = 1.f / (1.f + expf(-((zs0 + p_bz0) + p_ghz0)));
            float n0 = tanhf((ns0 + p_bn0) + r0 * p_ghn0);
            float h0 = (1.f - z0) * n0 + z0 * p_h0;
            float r1 = 1.f / (1.f + expf(-((rs1 + p_br1) + p_ghr1)));
            float z1 = 1.f / (1.f + expf(-((zs1 + p_bz1) + p_ghz1)));
            float n1 = tanhf((ns1 + p_bn1) + r1 * p_ghn1);
            float h1 = (1.f - z1) * n1 + z1 * p_h1;
            __stcg(&g_xbuf[(l + 1) & 1][j0], h0);
            __stcg(&g_xbuf[(l + 1) & 1][j1], h1);
            out[VOC + l * H + j0] = h0;     // hidden_new output
            out[VOC + l * H + j1] = h1;
        }
        __threadfence();
        if (l < NL - 1) {
            cl_arrive();
            // ---- window: gh(l+1) + wih(l+1) + scalars (x-independent) ------
            {
                const float* whh = gru_whh + (size_t)(l + 1) * 3 * H * H;
                const float4* h4 = (const float4*)(hidden + (l + 1) * H);
                float4 ha = __ldg(h4 + lane), hb = __ldg(h4 + lane + 32);
                const float4* vr0 = (const float4*)(whh + (size_t)j0 * H);
                const float4* vz0 = (const float4*)(whh + (size_t)(H + j0) * H);
                const float4* vn0 = (const float4*)(whh + (size_t)(2 * H + j0) * H);
                const float4* vr1 = (const float4*)(whh + (size_t)j1 * H);
                const float4* vz1 = (const float4*)(whh + (size_t)(H + j1) * H);
                const float4* vn1 = (const float4*)(whh + (size_t)(2 * H + j1) * H);
                float hr0 = dot4f(__ldg(vr0 + lane), ha) + dot4f(__ldg(vr0 + lane + 32), hb);
                float hz0 = dot4f(__ldg(vz0 + lane), ha) + dot4f(__ldg(vz0 + lane + 32), hb);
                float hn0 = dot4f(__ldg(vn0 + lane), ha) + dot4f(__ldg(vn0 + lane + 32), hb);
                float hr1 = dot4f(__ldg(vr1 + lane), ha) + dot4f(__ldg(vr1 + lane + 32), hb);
                float hz1 = dot4f(__ldg(vz1 + lane), ha) + dot4f(__ldg(vz1 + lane + 32), hb);
                float hn1 = dot4f(__ldg(vn1 + lane), ha) + dot4f(__ldg(vn1 + lane + 32), hb);
                float g1 = red4(hr0, hz0, hn0, 0.f, lane);
                float g2 = red4(hr1, hz1, hn1, 0.f, lane);
                p_ghr0 = __shfl_sync(0xffffffffu, g1, 0)  + __ldg(gru_bhh + ((l + 1) * 3 + 0) * H + j0);
                p_ghz0 = __shfl_sync(0xffffffffu, g1, 8)  + __ldg(gru_bhh + ((l + 1) * 3 + 1) * H + j0);
                p_ghn0 = __shfl_sync(0xffffffffu, g1, 16) + __ldg(gru_bhh + ((l + 1) * 3 + 2) * H + j0);
                p_ghr1 = __shfl_sync(0xffffffffu, g2, 0)  + __ldg(gru_bhh + ((l + 1) * 3 + 0) * H + j1);
                p_ghz1 = __shfl_sync(0xffffffffu, g2, 8)  + __ldg(gru_bhh + ((l + 1) * 3 + 1) * H + j1);
                p_ghn1 = __shfl_sync(0xffffffffu, g2, 16) + __ldg(gru_bhh + ((l + 1) * 3 + 2) * H + j1);
                const float* wih = gru_wih + (size_t)(l + 1) * 3 * H * H;
                const float4* r0p = (const float4*)(wih + (size_t)j0 * H);
                const float4* z0p = (const float4*)(wih + (size_t)(H + j0) * H);
                const float4* n0p = (const float4*)(wih + (size_t)(2 * H + j0) * H);
                const float4* r1p = (const float4*)(wih + (size_t)j1 * H);
                const float4* z1p = (const float4*)(wih + (size_t)(H + j1) * H);
                const float4* n1p = (const float4*)(wih + (size_t)(2 * H + j1) * H);
                W[0] = __ldg(r0p + lane); W[1] = __ldg(r0p + lane + 32);
                W[2] = __ldg(z0p + lane); W[3] = __ldg(z0p + lane + 32);
                W[4] = __ldg(n0p + lane); W[5] = __ldg(n0p + lane + 32);
                W[6] = __ldg(r1p + lane); W[7] = __ldg(r1p + lane + 32);
                W[8] = __ldg(z1p + lane); W[9] = __ldg(z1p + lane + 32);
                W[10] = __ldg(n1p + lane); W[11] = __ldg(n1p + lane + 32);
                p_br0 = __ldg(gru_bih + ((l + 1) * 3 + 0) * H + j0);
                p_bz0 = __ldg(gru_bih + ((l + 1) * 3 + 1) * H + j0);
                p_bn0 = __ldg(gru_bih + ((l + 1) * 3 + 2) * H + j0);
                p_br1 = __ldg(gru_bih + ((l + 1) * 3 + 0) * H + j1);
                p_bz1 = __ldg(gru_bih + ((l + 1) * 3 + 1) * H + j1);
                p_bn1 = __ldg(gru_bih + ((l + 1) * 3 + 2) * H + j1);
                p_h0 = __ldg(hidden + (l + 1) * H + j0);
                p_h1 = __ldg(hidden + (l + 1) * H + j1);
            }
            cl_wait();
        }
    }
    pdl_trigger();
    // attn_weights output (off critical path)
    if (bid == 0 && tid < SEQ) out[VOC + NL * H + tid] = s_aw[tid];
}

// ====================== K2: GEMV + per-block (m,s) (grid 148) ===============
__global__ void __launch_bounds__(TPB, 1)
k_gemv(const float* __restrict__ out_w,
       const float* __restrict__ out_b,
       float* __restrict__ out)
{
    const int tid = threadIdx.x, bid = blockIdx.x;
    const int wid = tid >> 5, lane = tid & 31;
    __shared__ __align__(16) float s_x[H];
    __shared__ float s_ms[2 * NWARP];

    const int gwid = bid * NWARP + wid;
    const int rown = lane >> 2;
    const bool own = (lane & 3) == 0;

    // ---- x-independent prologue: iteration-0 tiles + bias (PDL-hidden) -----
    float4 A0[16];
    {
        int r0 = gwid * 8;
        #pragma unroll
        for (int i = 0; i < 8; i++) {
            int row = r0 + i; if (row > VOC - 1) row = VOC - 1;
            const float4* wr = (const float4*)(out_w + (size_t)row * H);
            A0[2 * i]     = __ldg(wr + lane);
            A0[2 * i + 1] = __ldg(wr + lane + 32);
        }
    }
    float bias0 = 0.f;
    {
        int myrow = gwid * 8 + rown;
        if (own && myrow < VOC) bias0 = __ldg(out_b + myrow);
    }
    pdl_wait();

    if (tid < H) s_x[tid] = __ldcg(&g_xbuf[0][tid]);   // NL even -> buf 0
    __syncthreads();
    const float4* x4 = (const float4*)s_x;
    float4 xa = x4[lane], xb = x4[lane + 32];
    float mM = -1e30f, sS = 0.f;

    // ---- iteration 0 from preloaded tiles ----------------------------------
    {
        int r0 = gwid * 8;
        int myrow = r0 + rown;
        float d[8];
        #pragma unroll
        for (int i = 0; i < 8; i++)
            d[i] = dot4f(A0[2 * i], xa) + dot4f(A0[2 * i + 1], xb);
        float v = red8(d, lane);
        if (own && myrow < VOC) {
            v += bias0;
            out[myrow] = v;
            float m2 = fmaxf(mM, v);
            sS = sS * expf(mM - m2) + expf(v - m2);
            mM = m2;
        }
    }
    // ---- iterations 1..2 ----------------------------------------------------
    #pragma unroll 1
    for (int it = 1; it < GEMV_ITERS; it++) {
        int r0 = (it * GEMV_TOTW + gwid) * 8;
        int myrow = r0 + rown;
        float bias = (own && myrow < VOC) ? __ldg(out_b + myrow) : 0.f;
        float d[8];
        #pragma unroll
        for (int i = 0; i < 8; i++) {
            int row = r0 + i;
            float s = 0.f;
            if (row < VOC) {
                const float4* wr = (const float4*)(out_w + (size_t)row * H);
                float4 a0 = __ldg(wr + lane), a1 = __ldg(wr + lane + 32);
                s = dot4f(a0, xa) + dot4f(a1, xb);
            }
            d[i] = s;
        }
        float v = red8(d, lane);
        if (own && myrow < VOC) {
            v += bias;
            out[myrow] = v;
            float m2 = fmaxf(mM, v);
            sS = sS * expf(mM - m2) + expf(v - m2);
            mM = m2;
        }
    }
    #pragma unroll
    for (int o = 16; o; o >>= 1) {
        float om = __shfl_xor_sync(0xffffffffu, mM, o);
        float os = __shfl_xor_sync(0xffffffffu, sS, o);
        float m2 = fmaxf(mM, om);
        sS = sS * expf(mM - m2) + os * expf(om - m2);
        mM = m2;
    }
    if (lane == 0) { s_ms[wid] = mM; s_ms[NWARP + wid] = sS; }
    __syncthreads();
    if (tid == 0) {
        float M = s_ms[0], S = s_ms[NWARP];
        #pragma unroll
        for (int w = 1; w < NWARP; w++) {
            float m2 = fmaxf(M, s_ms[w]);
            S = S * expf(M - m2) + s_ms[NWARP + w] * expf(s_ms[w] - m2);
            M = m2;
        }
        g_red[bid] = make_float2(M, S);
    }
    __threadfence();
    pdl_trigger();
}

// ====================== K3: finalize lse + subtract (grid 148) ==============
__global__ void __launch_bounds__(TPB, 1)
k_final(float* __restrict__ out)
{
    const int tid = threadIdx.x, bid = blockIdx.x;
    const int wid = tid >> 5, lane = tid & 31;
    __shared__ float s_lse;

    pdl_wait();
    if (wid == 0) {
        float M = -1e30f, S = 0.f;
        for (int k = lane; k < GEMV_GRID; k += 32) {
            float2 p = g_red[k];
            float m2 = fmaxf(M, p.x);
            S = S * expf(M - m2) + p.y * expf(p.x - m2);
            M = m2;
        }
        #pragma unroll
        for (int o = 16; o; o >>= 1) {
            float om = __shfl_xor_sync(0xffffffffu, M, o);
            float os = __shfl_xor_sync(0xffffffffu, S, o);
            float m2 = fmaxf(M, om);
            S = S * expf(M - m2) + os * expf(om - m2);
            M = m2;
        }
        if (lane == 0) s_lse = M + logf(S);
    }
    __syncthreads();
    float lse = s_lse;
    int i = bid * TPB + tid;          // 148*512 = 75776 >= VOC, one pass
    if (i < VOC) out[i] -= lse;
}

// ---------------- host: PDL launch helper -----------------------------------
static void launch_pdl(const void* func, dim3 grid, dim3 block, void** args) {
    cudaLaunchConfig_t cfg = {};
    cfg.gridDim = grid;
    cfg.blockDim = block;
    cfg.dynamicSmemBytes = 0;
    cfg.stream = 0;
    cudaLaunchAttribute attr[1];
    attr[0].id = cudaLaunchAttributeProgrammaticStreamSerialization;
    attr[0].val.programmaticStreamSerializationAllowed = 1;
    cfg.attrs = attr;
    cfg.numAttrs = 1;
    cudaLaunchKernelExC(&cfg, func, args);
}

extern "C" void kernel_launch(void* const* d_in, const int* in_sizes, int n_in,
                              void* d_out, int out_size) {
    const int*   token   = (const int*)d_in[0];
    const float* hidden  = (const float*)d_in[1];
    const float* enc     = (const float*)d_in[2];
    const float* emb     = (const float*)d_in[3];
    const float* attn_w  = (const float*)d_in[4];
    const float* attn_b  = (const float*)d_in[5];
    const float* comb_w  = (const float*)d_in[6];
    const float* comb_b  = (const float*)d_in[7];
    const float* gru_wih = (const float*)d_in[8];
    const float* gru_whh = (const float*)d_in[9];
    const float* gru_bih = (const float*)d_in[10];
    const float* gru_bhh = (const float*)d_in[11];
    const float* out_w   = (const float*)d_in[12];
    const float* out_b   = (const float*)d_in[13];
    float* out = (float*)d_out;

    k_chain<<<CHB, TPB>>>(token, hidden, enc, emb, attn_w, attn_b,
                          comb_w, comb_b, gru_wih, gru_whh, gru_bih, gru_bhh,
                          out);
    {
        void* a[] = {(void*)&out_w, (void*)&out_b, (void*)&out};
        launch_pdl((const void*)k_gemv, dim3(GEMV_GRID), dim3(TPB), a);
    }
    {
        void* a[] = {(void*)&out};
        launch_pdl((const void*)k_final, dim3(GEMV_GRID), dim3(TPB), a);
    }
}